// round 1
// baseline (speedup 1.0000x reference)
#include <cuda_runtime.h>
#include <math.h>

#define MM 2048
#define NN 2048
#define PP (MM * NN)

// Scratch (allocation-free rule: __device__ globals)
__device__ float g_y[2 * PP];   // plane 0: horizontal, plane 1: vertical
__device__ float g_w[2 * PP];
__device__ float g_x[PP];
__device__ float g_xt[PP];

__device__ __forceinline__ float clamp1(float v) {
    return fminf(1.0f, fmaxf(-1.0f, v));
}

// constants
#define C_SIGMA (1.0f / (7.0f * 0.01f))
#define C_TAU   (0.01f)
#define C_LT    (4.0f * 0.01f)        // LAMBDA_ROF * TAU
#define C_INV   (1.0f / 1.04f)        // 1/(1 + LAMBDA_ROF*TAU)

// ---------------------------------------------------------------------------
// Init: y = forward_grad(img); w = w1 + w2*exp(-|y|); x = xt = img
// ---------------------------------------------------------------------------
__global__ void init_k(const float* __restrict__ img,
                       const float* __restrict__ w1p,
                       const float* __restrict__ w2p) {
    int i = blockIdx.y;
    int j = (blockIdx.x * blockDim.x + threadIdx.x) * 4;
    int idx = i * NN + j;

    float4 v = *(const float4*)(img + idx);
    float xr = 0.0f;
    bool has_r = (j + 4 < NN);
    if (has_r) xr = img[idx + 4];

    float gh0 = v.y - v.x;
    float gh1 = v.z - v.y;
    float gh2 = v.w - v.z;
    float gh3 = has_r ? (xr - v.w) : 0.0f;

    float4 gv = make_float4(0.f, 0.f, 0.f, 0.f);
    if (i < MM - 1) {
        float4 b = *(const float4*)(img + idx + NN);
        gv.x = b.x - v.x; gv.y = b.y - v.y; gv.z = b.z - v.z; gv.w = b.w - v.w;
    }

    float w1 = w1p[0], w2 = w2p[0];
    float4 wh, wv;
    wh.x = w1 + w2 * expf(-fabsf(gh0));
    wh.y = w1 + w2 * expf(-fabsf(gh1));
    wh.z = w1 + w2 * expf(-fabsf(gh2));
    wh.w = w1 + w2 * expf(-fabsf(gh3));
    wv.x = w1 + w2 * expf(-fabsf(gv.x));
    wv.y = w1 + w2 * expf(-fabsf(gv.y));
    wv.z = w1 + w2 * expf(-fabsf(gv.z));
    wv.w = w1 + w2 * expf(-fabsf(gv.w));

    *(float4*)(g_y + idx)       = make_float4(gh0, gh1, gh2, gh3);
    *(float4*)(g_y + PP + idx)  = gv;
    *(float4*)(g_w + idx)       = wh;
    *(float4*)(g_w + PP + idx)  = wv;
    *(float4*)(g_x + idx)       = v;
    *(float4*)(g_xt + idx)      = v;
}

// ---------------------------------------------------------------------------
// Dual: y = clamp(y + SIGMA * w * forward_grad(xt), -1, 1)
// ---------------------------------------------------------------------------
__global__ void dual_k() {
    int i = blockIdx.y;
    int j = (blockIdx.x * blockDim.x + threadIdx.x) * 4;
    int idx = i * NN + j;

    float4 v = *(const float4*)(g_xt + idx);
    bool has_r = (j + 4 < NN);
    float xr = has_r ? g_xt[idx + 4] : 0.0f;

    float gh0 = v.y - v.x;
    float gh1 = v.z - v.y;
    float gh2 = v.w - v.z;
    float gh3 = has_r ? (xr - v.w) : 0.0f;

    float4 gv = make_float4(0.f, 0.f, 0.f, 0.f);
    if (i < MM - 1) {
        float4 b = *(const float4*)(g_xt + idx + NN);
        gv.x = b.x - v.x; gv.y = b.y - v.y; gv.z = b.z - v.z; gv.w = b.w - v.w;
    }

    float4 yh = *(const float4*)(g_y + idx);
    float4 yv = *(const float4*)(g_y + PP + idx);
    float4 wh = *(const float4*)(g_w + idx);
    float4 wv = *(const float4*)(g_w + PP + idx);

    yh.x = clamp1(fmaf(C_SIGMA * wh.x, gh0, yh.x));
    yh.y = clamp1(fmaf(C_SIGMA * wh.y, gh1, yh.y));
    yh.z = clamp1(fmaf(C_SIGMA * wh.z, gh2, yh.z));
    yh.w = clamp1(fmaf(C_SIGMA * wh.w, gh3, yh.w));
    yv.x = clamp1(fmaf(C_SIGMA * wv.x, gv.x, yv.x));
    yv.y = clamp1(fmaf(C_SIGMA * wv.y, gv.y, yv.y));
    yv.z = clamp1(fmaf(C_SIGMA * wv.z, gv.z, yv.z));
    yv.w = clamp1(fmaf(C_SIGMA * wv.w, gv.w, yv.w));

    *(float4*)(g_y + idx)      = yh;
    *(float4*)(g_y + PP + idx) = yv;
}

// ---------------------------------------------------------------------------
// Primal: x_new = (x + TAU*div(w*y) + LT*img) / 1.04 ; xt = 1.5*x_new - 0.5*x
// div(i,j) = wyh(i,j) - wyh(i,j-1) + wyv(i,j) - wyv(i-1,j), OOB = 0
// ---------------------------------------------------------------------------
__global__ void primal_k(const float* __restrict__ img,
                         float* __restrict__ out, int is_last) {
    int i = blockIdx.y;
    int j = (blockIdx.x * blockDim.x + threadIdx.x) * 4;
    int idx = i * NN + j;

    float4 yh = *(const float4*)(g_y + idx);
    float4 wh = *(const float4*)(g_w + idx);
    float4 yv = *(const float4*)(g_y + PP + idx);
    float4 wv = *(const float4*)(g_w + PP + idx);

    float a0 = wh.x * yh.x;
    float a1 = wh.y * yh.y;
    float a2 = wh.z * yh.z;
    float a3 = wh.w * yh.w;

    float al = 0.0f;
    if (j > 0) al = g_w[idx - 1] * g_y[idx - 1];

    float b0 = wv.x * yv.x;
    float b1 = wv.y * yv.y;
    float b2 = wv.z * yv.z;
    float b3 = wv.w * yv.w;

    float4 u = make_float4(0.f, 0.f, 0.f, 0.f);
    if (i > 0) {
        float4 yu = *(const float4*)(g_y + PP + idx - NN);
        float4 wu = *(const float4*)(g_w + PP + idx - NN);
        u.x = wu.x * yu.x; u.y = wu.y * yu.y; u.z = wu.z * yu.z; u.w = wu.w * yu.w;
    }

    float d0 = a0 - al + b0 - u.x;
    float d1 = a1 - a0 + b1 - u.y;
    float d2 = a2 - a1 + b2 - u.z;
    float d3 = a3 - a2 + b3 - u.w;

    float4 x  = *(const float4*)(g_x + idx);
    float4 f  = *(const float4*)(img + idx);

    float4 xn;
    xn.x = (fmaf(C_TAU, d0, x.x) + C_LT * f.x) * C_INV;
    xn.y = (fmaf(C_TAU, d1, x.y) + C_LT * f.y) * C_INV;
    xn.z = (fmaf(C_TAU, d2, x.z) + C_LT * f.z) * C_INV;
    xn.w = (fmaf(C_TAU, d3, x.w) + C_LT * f.w) * C_INV;

    float4 xt;
    xt.x = 1.5f * xn.x - 0.5f * x.x;
    xt.y = 1.5f * xn.y - 0.5f * x.y;
    xt.z = 1.5f * xn.z - 0.5f * x.z;
    xt.w = 1.5f * xn.w - 0.5f * x.w;

    *(float4*)(g_x + idx) = xn;
    float* dst = is_last ? out : g_xt;
    *(float4*)(dst + idx) = xt;
}

extern "C" void kernel_launch(void* const* d_in, const int* in_sizes, int n_in,
                              void* d_out, int out_size) {
    // Identify inputs by size (img is the only big one; w1 then w2 in order)
    const float* img = nullptr;
    const float* w1 = nullptr;
    const float* w2 = nullptr;
    for (int k = 0; k < n_in; k++) {
        if (in_sizes[k] >= MM * NN) {
            img = (const float*)d_in[k];
        } else if (!w1) {
            w1 = (const float*)d_in[k];
        } else if (!w2) {
            w2 = (const float*)d_in[k];
        }
    }
    float* out = (float*)d_out;

    dim3 blk(128, 1, 1);
    dim3 grd(NN / 4 / 128, MM, 1);

    init_k<<<grd, blk>>>(img, w1, w2);
    for (int it = 0; it < 10; it++) {
        dual_k<<<grd, blk>>>();
        primal_k<<<grd, blk>>>(img, out, it == 9 ? 1 : 0);
    }
}